// round 10
// baseline (speedup 1.0000x reference)
#include <cuda_runtime.h>
#include <cuda_fp16.h>
#include <cstdint>

#define NB   8192
#define NFLD 64
#define DDIM 128

// ---------------- device globals (no allocation allowed) ----------------
__device__ __align__(16) __half g_Sh [(size_t)NB * NFLD * NFLD];   // S fp16, 64 MB
__device__ __align__(16) __half g_Wth[(size_t)NFLD * DDIM * NFLD]; // Wt[i][d][j] fp16
__device__ __align__(16) __half g_Kwh[DDIM * DDIM];                // fp16 K_w[e][d]
__device__ __align__(16) __half g_Qwh[DDIM * DDIM];                // fp16 Q_w[e][d]

// ---------------- helpers ----------------
__device__ __forceinline__ uint32_t smem_u32(const void* p) {
    uint32_t a;
    asm("{ .reg .u64 t; cvta.to.shared.u64 t, %1; cvt.u32.u64 %0, t; }"
        : "=r"(a) : "l"(p));
    return a;
}
__device__ __forceinline__ unsigned pk(float a, float b) {
    __half2 h = __floats2half2_rn(a, b);
    return *reinterpret_cast<unsigned*>(&h);
}
__device__ __forceinline__ uint4 cvt8(float4 a, float4 b) {
    return make_uint4(pk(a.x, a.y), pk(a.z, a.w), pk(b.x, b.y), pk(b.z, b.w));
}

// ldmatrix x4: loads 4 8x8 fp16 matrices, one 16B row address per lane
__device__ __forceinline__ void ldsm4(uint32_t* r, uint32_t addr) {
    asm volatile("ldmatrix.sync.aligned.m8n8.x4.shared.b16 {%0,%1,%2,%3}, [%4];"
                 : "=r"(r[0]), "=r"(r[1]), "=r"(r[2]), "=r"(r[3]) : "r"(addr));
}
// D += A*B : m16n8k16 fp16 in, f32 accum
__device__ __forceinline__ void mma16(float* c, const uint32_t* a, const uint32_t* b) {
    asm volatile("mma.sync.aligned.m16n8k16.row.col.f32.f16.f16.f32 "
                 "{%0,%1,%2,%3},{%4,%5,%6,%7},{%8,%9},{%0,%1,%2,%3};"
                 : "+f"(c[0]), "+f"(c[1]), "+f"(c[2]), "+f"(c[3])
                 : "r"(a[0]), "r"(a[1]), "r"(a[2]), "r"(a[3]), "r"(b[0]), "r"(b[1]));
}
// A-frag (16x16 tile at row0, half-col colh) from row-major fp16 smem
__device__ __forceinline__ uint32_t lda(uint32_t base, int ld, int row0, int colh, int lane) {
    return base + 2u * (uint32_t)((row0 + (lane & 15)) * ld + colh + ((lane >> 4) << 3));
}
// B-frags x4 (n16 x k16 at n0, k0) from row-major B^T[n][k] fp16 smem
__device__ __forceinline__ uint32_t ldb(uint32_t base, int ld, int n0, int k0, int lane) {
    int row  = n0 + ((lane >> 4) << 3) + (lane & 7);
    int koff = ((lane >> 3) & 1) << 3;
    return base + 2u * (uint32_t)(row * ld + k0 + koff);
}
// write a c-frag (4 f32) as fp16 pairs at (row,col) and (row+8,col)
__device__ __forceinline__ void dumph(char* smb, int ld, int row, int col, const float* c) {
    *reinterpret_cast<unsigned*>(smb + 2 * (row * ld + col))       = pk(c[0], c[1]);
    *reinterpret_cast<unsigned*>(smb + 2 * ((row + 8) * ld + col)) = pk(c[2], c[3]);
}

// ---------------- prep: fp16 weights + W transpose ----------------
__global__ void prep(const float* __restrict__ W, const float* __restrict__ Kw,
                     const float* __restrict__ Qw) {
    extern __shared__ __half th[];            // 64 x 136
    const int bid = blockIdx.x, tid = threadIdx.x;
    if (bid < 64) {
        const float4* W4 = reinterpret_cast<const float4*>(W) + (size_t)bid * 2048;
        #pragma unroll
        for (int it = 0; it < 8; it++) {
            int x = tid + it * 256;            // 0..2047
            float4 v = W4[x];
            int j = x >> 5, d4 = (x & 31) * 4;
            __half* p = th + j * 136 + d4;
            p[0] = __float2half_rn(v.x); p[1] = __float2half_rn(v.y);
            p[2] = __float2half_rn(v.z); p[3] = __float2half_rn(v.w);
        }
        __syncthreads();
        #pragma unroll
        for (int it = 0; it < 4; it++) {
            int x = tid + it * 256;            // d = x>>3, j8 = x&7
            int d = x >> 3, j0 = (x & 7) * 8;
            __half tmp[8];
            #pragma unroll
            for (int t = 0; t < 8; t++) tmp[t] = th[(j0 + t) * 136 + d];
            reinterpret_cast<uint4*>(g_Wth)[(size_t)bid * 1024 + x] =
                *reinterpret_cast<uint4*>(tmp);
        }
    } else {
        const float* src = (bid == 64) ? Kw : Qw;
        __half2* dst = reinterpret_cast<__half2*>((bid == 64) ? g_Kwh : g_Qwh);
        #pragma unroll
        for (int it = 0; it < 16; it++) {
            int x = tid + it * 256;            // 0..4095 float4
            float4 v = reinterpret_cast<const float4*>(src)[x];
            dst[2 * x]     = __floats2half2_rn(v.x, v.y);
            dst[2 * x + 1] = __floats2half2_rn(v.z, v.w);
        }
    }
}

// ---------------- k1: per 2 batches — Kf = F2@Kw^T, S = diag(F2@Kf^T) ----------------
// smem: smF [128][136] fp16 (F2, then S-stage [128][72]),
//       smB [128][136] fp16 (Kw, then Kf)
#define K1_OFF_B 34816
#define K1_SMEM  69632

__global__ void __launch_bounds__(256, 2) k1(const float* __restrict__ F) {
    extern __shared__ char sm[];
    char* smF = sm;
    char* smB = sm + K1_OFF_B;
    const uint32_t ubF = smem_u32(smF), ubB = smem_u32(smB);
    const int tid = threadIdx.x, wid = tid >> 5, lane = tid & 31;
    const int wm = wid >> 2, wn = wid & 3;
    const int r0 = lane >> 2, cO = 2 * (lane & 3);

    // ---- stage F2 (f32 -> fp16) and Kw ----
    {
        const float4* F4 = reinterpret_cast<const float4*>(F) + (size_t)blockIdx.x * 4096;
        #pragma unroll
        for (int it = 0; it < 8; it++) {
            int x = tid + it * 256;            // 0..2047 uint4
            int u = x >> 4, c8 = x & 15;
            float4 a = F4[u * 32 + c8 * 2], b = F4[u * 32 + c8 * 2 + 1];
            *reinterpret_cast<uint4*>(smF + 2 * (u * 136 + c8 * 8)) = cvt8(a, b);
            *reinterpret_cast<uint4*>(smB + 2 * (u * 136 + c8 * 8)) =
                reinterpret_cast<const uint4*>(g_Kwh)[x];
        }
    }
    __syncthreads();

    // ---- GEMM1: Kf = F2 @ Kw^T (128x128, K=128) ----
    float accK[4][4][4];
    #pragma unroll
    for (int mt = 0; mt < 4; mt++)
        #pragma unroll
        for (int nt = 0; nt < 4; nt++)
            #pragma unroll
            for (int q = 0; q < 4; q++) accK[mt][nt][q] = 0.f;
    #pragma unroll
    for (int ks = 0; ks < 8; ks++) {
        uint32_t a[4][4], bq[2][4];
        #pragma unroll
        for (int mt = 0; mt < 4; mt++)
            ldsm4(a[mt], lda(ubF, 136, wm * 64 + mt * 16, ks * 16, lane));
        #pragma unroll
        for (int bt = 0; bt < 2; bt++)
            ldsm4(bq[bt], ldb(ubB, 136, wn * 32 + bt * 16, ks * 16, lane));
        #pragma unroll
        for (int mt = 0; mt < 4; mt++)
            #pragma unroll
            for (int nt = 0; nt < 4; nt++)
                mma16(accK[mt][nt], a[mt], &bq[nt >> 1][(nt & 1) * 2]);
    }
    __syncthreads();

    // ---- dump Kf -> smB fp16 (overwrites Kw) ----
    #pragma unroll
    for (int mt = 0; mt < 4; mt++)
        #pragma unroll
        for (int nt = 0; nt < 4; nt++)
            dumph(smB, 136, wm * 64 + mt * 16 + r0, wn * 32 + nt * 8 + cO, accK[mt][nt]);
    __syncthreads();

    // ---- GEMM2: S diag blocks (per batch 64x64, K=128) ----
    float accS[2][4][4];
    #pragma unroll
    for (int mt = 0; mt < 2; mt++)
        #pragma unroll
        for (int nt = 0; nt < 4; nt++)
            #pragma unroll
            for (int q = 0; q < 4; q++) accS[mt][nt][q] = 0.f;
    const int h = wid >> 2, ww = wid & 3;
    const int m0  = h * 64 + (ww & 1) * 32;        // A rows (i, batch-stacked)
    const int n0j = h * 64 + (ww >> 1) * 32;       // Kf rows (j, batch-stacked)
    #pragma unroll
    for (int ks = 0; ks < 8; ks++) {
        uint32_t a2[2][4], b2[2][4];
        #pragma unroll
        for (int mt = 0; mt < 2; mt++)
            ldsm4(a2[mt], lda(ubF, 136, m0 + mt * 16, ks * 16, lane));
        #pragma unroll
        for (int bt = 0; bt < 2; bt++)
            ldsm4(b2[bt], ldb(ubB, 136, n0j + bt * 16, ks * 16, lane));
        #pragma unroll
        for (int mt = 0; mt < 2; mt++)
            #pragma unroll
            for (int nt = 0; nt < 4; nt++)
                mma16(accS[mt][nt], a2[mt], &b2[nt >> 1][(nt & 1) * 2]);
    }
    __syncthreads();   // all reads of smF done -> reuse as S stage [128][72]

    #pragma unroll
    for (int mt = 0; mt < 2; mt++)
        #pragma unroll
        for (int nt = 0; nt < 4; nt++)
            dumph(smF, 72, m0 + mt * 16 + r0, (ww >> 1) * 32 + nt * 8 + cO, accS[mt][nt]);
    __syncthreads();

    // ---- bulk store S ----
    #pragma unroll
    for (int it = 0; it < 4; it++) {
        int x = tid + it * 256;                // 0..1023 uint4
        int bt = x >> 9, rem = x & 511, i = rem >> 3, c8 = rem & 7;
        uint4 v = *reinterpret_cast<const uint4*>(smF + 2 * ((bt * 64 + i) * 72 + c8 * 8));
        reinterpret_cast<uint4*>(g_Sh)[(size_t)blockIdx.x * 1024 + bt * 512 + i * 8 + c8] = v;
    }
}

// ---------------- k2: out[:,i,:] = S[:,i,:]@Wt[i] + F[:,i,:]@Qw^T ----------------
// smem: smS [128][72], smW [128][72], smFq [128][136], smQ [128][136]
#define K2_OFF_W 18432
#define K2_OFF_F 36864
#define K2_OFF_Q 71680
#define K2_SMEM  106496

__global__ void __launch_bounds__(256, 2) k2(const float* __restrict__ F,
                                             float* __restrict__ out) {
    extern __shared__ char sm[];
    char* smS  = sm;
    char* smW  = sm + K2_OFF_W;
    char* smFq = sm + K2_OFF_F;
    char* smQ  = sm + K2_OFF_Q;
    const uint32_t ubS = smem_u32(smS), ubW = smem_u32(smW);
    const uint32_t ubFq = smem_u32(smFq), ubQ = smem_u32(smQ);
    const int tid = threadIdx.x, wid = tid >> 5, lane = tid & 31;
    const int wm = wid >> 2, wn = wid & 3;
    const int r0 = lane >> 2, cO = 2 * (lane & 3);
    const int i = blockIdx.y;
    const int b0 = blockIdx.x * 128;

    // ---- stage S, Wt[i] ----
    #pragma unroll
    for (int it = 0; it < 4; it++) {
        int x = tid + it * 256;                // 0..1023
        int u = x >> 3, c8 = x & 7;
        uint4 vs = reinterpret_cast<const uint4*>(g_Sh)[((size_t)(b0 + u) * NFLD + i) * 8 + c8];
        *reinterpret_cast<uint4*>(smS + 2 * (u * 72 + c8 * 8)) = vs;
        uint4 vw = reinterpret_cast<const uint4*>(g_Wth)[(size_t)i * 1024 + x];
        *reinterpret_cast<uint4*>(smW + 2 * (u * 72 + c8 * 8)) = vw;
    }
    // ---- stage F rows (f32 -> fp16) and Qw ----
    {
        const float4* F4 = reinterpret_cast<const float4*>(F);
        #pragma unroll
        for (int it = 0; it < 8; it++) {
            int x = tid + it * 256;            // 0..2047
            int u = x >> 4, c8 = x & 15;
            const float4* fp = F4 + ((size_t)(b0 + u) * NFLD + i) * 32 + c8 * 2;
            *reinterpret_cast<uint4*>(smFq + 2 * (u * 136 + c8 * 8)) = cvt8(fp[0], fp[1]);
            *reinterpret_cast<uint4*>(smQ + 2 * (u * 136 + c8 * 8)) =
                reinterpret_cast<const uint4*>(g_Qwh)[x];
        }
    }
    __syncthreads();

    float acc[4][4][4];
    #pragma unroll
    for (int mt = 0; mt < 4; mt++)
        #pragma unroll
        for (int nt = 0; nt < 4; nt++)
            #pragma unroll
            for (int q = 0; q < 4; q++) acc[mt][nt][q] = 0.f;

    // ---- Phase A: S @ Wt[i]  (K = 64) ----
    #pragma unroll
    for (int ks = 0; ks < 4; ks++) {
        uint32_t a[4][4], bq[2][4];
        #pragma unroll
        for (int mt = 0; mt < 4; mt++)
            ldsm4(a[mt], lda(ubS, 72, wm * 64 + mt * 16, ks * 16, lane));
        #pragma unroll
        for (int bt = 0; bt < 2; bt++)
            ldsm4(bq[bt], ldb(ubW, 72, wn * 32 + bt * 16, ks * 16, lane));
        #pragma unroll
        for (int mt = 0; mt < 4; mt++)
            #pragma unroll
            for (int nt = 0; nt < 4; nt++)
                mma16(acc[mt][nt], a[mt], &bq[nt >> 1][(nt & 1) * 2]);
    }
    // ---- Phase B: F @ Qw^T  (K = 128) ----
    #pragma unroll
    for (int ks = 0; ks < 8; ks++) {
        uint32_t a[4][4], bq[2][4];
        #pragma unroll
        for (int mt = 0; mt < 4; mt++)
            ldsm4(a[mt], lda(ubFq, 136, wm * 64 + mt * 16, ks * 16, lane));
        #pragma unroll
        for (int bt = 0; bt < 2; bt++)
            ldsm4(bq[bt], ldb(ubQ, 136, wn * 32 + bt * 16, ks * 16, lane));
        #pragma unroll
        for (int mt = 0; mt < 4; mt++)
            #pragma unroll
            for (int nt = 0; nt < 4; nt++)
                mma16(acc[mt][nt], a[mt], &bq[nt >> 1][(nt & 1) * 2]);
    }
    __syncthreads();

    // ---- epilogue: stage f32 halves (over smS+smW), coalesced float4 stores ----
    float* Es = reinterpret_cast<float*>(sm);   // [128][68] f32
    #pragma unroll 1
    for (int hh = 0; hh < 2; hh++) {
        if (hh) __syncthreads();
        if ((wn >> 1) == hh) {
            #pragma unroll
            for (int mt = 0; mt < 4; mt++) {
                int row = wm * 64 + mt * 16 + r0;
                #pragma unroll
                for (int nt = 0; nt < 4; nt++) {
                    int cl = (wn & 1) * 32 + nt * 8 + cO;
                    *reinterpret_cast<float2*>(Es + row * 68 + cl) =
                        make_float2(acc[mt][nt][0], acc[mt][nt][1]);
                    *reinterpret_cast<float2*>(Es + (row + 8) * 68 + cl) =
                        make_float2(acc[mt][nt][2], acc[mt][nt][3]);
                }
            }
        }
        __syncthreads();
        #pragma unroll
        for (int it = 0; it < 8; it++) {
            int x = tid + it * 256;            // 0..2047
            int u = x >> 4, c4 = x & 15;
            float4 v = *reinterpret_cast<const float4*>(Es + u * 68 + c4 * 4);
            *reinterpret_cast<float4*>(
                out + ((size_t)(b0 + u) * NFLD + i) * DDIM + hh * 64 + c4 * 4) = v;
        }
    }
}

// ---------------- launch ----------------
extern "C" void kernel_launch(void* const* d_in, const int* in_sizes, int n_in,
                              void* d_out, int out_size) {
    const float* F  = (const float*)d_in[0];
    const float* W  = (const float*)d_in[1];
    const float* Kw = (const float*)d_in[2];
    const float* Qw = (const float*)d_in[3];
    float* out = (float*)d_out;

    cudaFuncSetAttribute(prep, cudaFuncAttributeMaxDynamicSharedMemorySize, 17408);
    cudaFuncSetAttribute(k1,   cudaFuncAttributeMaxDynamicSharedMemorySize, K1_SMEM);
    cudaFuncSetAttribute(k2,   cudaFuncAttributeMaxDynamicSharedMemorySize, K2_SMEM);

    prep<<<66, 256, 17408>>>(W, Kw, Qw);
    k1<<<NB / 2, 256, K1_SMEM>>>(F);
    dim3 g2(NB / 128, NFLD);
    k2<<<g2, 256, K2_SMEM>>>(F, out);
}